// round 10
// baseline (speedup 1.0000x reference)
#include <cuda_runtime.h>
#include <cuda_fp16.h>
#include <math.h>

#define B_    4096
#define T_    24
#define NN    7
#define DYNV  6
#define INV   11
#define H     64
#define FUT   48

#define BT    64            // threads per block, one batch element per block
#define HS    68            // padded row stride (floats)

typedef unsigned long long ull;

// LSTM weights: fp32 quad-packed [(kq*256 + c)*4 + q] = W[4kq+q][c]
__device__ float g_wih4[16 * 256 * 4];
__device__ float g_whh4[16 * 256 * 4];
// GCN / encoder / decoder-1 weights: fp16 quad-packed (fits everything in L1)
__device__ __half g_g1w_h[16 * 64 * 4];
__device__ __half g_g2w_h[16 * 64 * 4];
__device__ __half g_enc_h[3 * 64 * 4];   // k padded 11 -> 12
__device__ __half g_d1w_h[16 * 32 * 4];
__device__ float  g_d2w2[16 * 6 * 2];    // pair-packed fp32 (tiny)

__global__ void pack_weights(const float* __restrict__ w_ih, const float* __restrict__ w_hh,
                             const float* __restrict__ g1w,  const float* __restrict__ g2w,
                             const float* __restrict__ enc_w,
                             const float* __restrict__ d1w,  const float* __restrict__ d2w) {
    int i = blockIdx.x * blockDim.x + threadIdx.x;
    if (i < 16384) {
        int q = i & 3, gc = (i >> 2) & 255, kq = i >> 10;
        g_wih4[i] = w_ih[gc * 64 + 4 * kq + q];     // w_ih is [256][64]
        g_whh4[i] = w_hh[gc * 64 + 4 * kq + q];
    } else if (i < 16384 + 4096) {
        int j = i - 16384;
        int q = j & 3, c = (j >> 2) & 63, kq = j >> 8;
        g_g1w_h[j] = __float2half(g1w[(4 * kq + q) * 64 + c]);   // g1w is [64][64]
        g_g2w_h[j] = __float2half(g2w[(4 * kq + q) * 64 + c]);
    } else if (i < 16384 + 4096 + 768) {
        int j = i - 16384 - 4096;
        int q = j & 3, c = (j >> 2) & 63, kq = j >> 8;
        int k = 4 * kq + q;
        g_enc_h[j] = __float2half((k < INV) ? enc_w[k * 64 + c] : 0.f);
    } else if (i < 16384 + 4096 + 768 + 2048) {
        int j = i - 16384 - 4096 - 768;
        int q = j & 3, c = (j >> 2) & 31, kq = j >> 7;
        g_d1w_h[j] = __float2half(d1w[(4 * kq + q) * 32 + c]);
    } else if (i < 16384 + 4096 + 768 + 2048 + 192) {
        int j = i - (16384 + 4096 + 768 + 2048);
        int kp = j / 12, rr = j - kp * 12, d = rr >> 1, p = rr & 1;
        g_d2w2[j] = d2w[(2 * kp + p) * 6 + d];
    }
}

// ---------- helpers ----------
__device__ __forceinline__ ulonglong2 ldg4(const float* p) {
    return __ldg(reinterpret_cast<const ulonglong2*>(p));
}
__device__ __forceinline__ ulonglong2 lds4(const float* p) {
    return *reinterpret_cast<const ulonglong2*>(p);
}
__device__ __forceinline__ ull ldsm2(const float* p) { return *reinterpret_cast<const ull*>(p); }
__device__ __forceinline__ ull ldg2(const float* p)  { return __ldg(reinterpret_cast<const ull*>(p)); }
// Load 4 fp16 weights (8B), convert to two packed f32x2 operands.
__device__ __forceinline__ void ldgh4(const __half* p, ull& lo, ull& hi) {
    ull raw = __ldg(reinterpret_cast<const ull*>(p));
    __half2* h = reinterpret_cast<__half2*>(&raw);
    float2 f0 = __half22float2(h[0]);
    float2 f1 = __half22float2(h[1]);
    lo = *reinterpret_cast<ull*>(&f0);
    hi = *reinterpret_cast<ull*>(&f1);
}
__device__ __forceinline__ void ffma2(ull& d, ull a, ull b) {
    asm("fma.rn.f32x2 %0, %1, %2, %3;" : "=l"(d) : "l"(a), "l"(b), "l"(d));
}
__device__ __forceinline__ float hsum(ull v) {
    float2 f = *reinterpret_cast<float2*>(&v);
    return f.x + f.y;
}
__device__ __forceinline__ float sigm_f(float x) { return __fdividef(1.f, 1.f + __expf(-x)); }
__device__ __forceinline__ float tanh_f(float x) {
    float e = __expf(2.f * x);
    return 1.f - __fdividef(2.f, e + 1.f);
}

struct __align__(16) Smem {
    float xt[NN][12];
    float A[NN][HS];
    float Bv[NN][HS];
    float hx[NN][HS];
    float cx[NN][HS];
    float adjn[49];
    float deg[8];
    float pred[NN][DYNV];
    float stat[NN][8];
};

// GCN layer fused: out[i][c] = relu( sum_j adjn[i][j] * (in @ W)[j][c] + bias[c] )
// GEMM intermediate for column c stays in registers of thread c. fp16 weights.
__device__ __forceinline__ void gcn_fused(const Smem* s, const float (*in)[HS],
                                          const __half* __restrict__ wh,
                                          float (*out)[HS],
                                          const float* __restrict__ bias, int c) {
    ull acc[NN] = {};
    #pragma unroll
    for (int kq = 0; kq < 16; kq++) {
        ull wx, wy;
        ldgh4(&wh[(kq * 64 + c) * 4], wx, wy);
        #pragma unroll
        for (int r = 0; r < NN; r++) {
            ulonglong2 a = lds4(&in[r][4 * kq]);
            ffma2(acc[r], a.x, wx);
            ffma2(acc[r], a.y, wy);
        }
    }
    float bv[NN];
    #pragma unroll
    for (int r = 0; r < NN; r++) bv[r] = hsum(acc[r]);
    float bb = __ldg(&bias[c]);
    #pragma unroll
    for (int i = 0; i < NN; i++) {
        float a = bb;
        #pragma unroll
        for (int j = 0; j < NN; j++)
            a = fmaf(s->adjn[i * 7 + j], bv[j], a);
        out[i][c] = fmaxf(a, 0.f);
    }
}

// One cell step. xt filled+synced on entry; hx/cx updated+synced on exit.
__device__ __forceinline__ void cell(Smem* s, int c,
        const float* __restrict__ enc_b,
        const float* __restrict__ g1b, const float* __restrict__ g2b,
        const float* __restrict__ b_ih, const float* __restrict__ b_hh) {
    // encoder -> A  (fp16 weights)
    {
        ull acc[NN] = {};
        #pragma unroll
        for (int kq = 0; kq < 3; kq++) {
            ull wx, wy;
            ldgh4(&g_enc_h[(kq * 64 + c) * 4], wx, wy);
            #pragma unroll
            for (int r = 0; r < NN; r++) {
                ulonglong2 a = lds4(&s->xt[r][4 * kq]);
                ffma2(acc[r], a.x, wx);
                ffma2(acc[r], a.y, wy);
            }
        }
        float bb = __ldg(&enc_b[c]);
        #pragma unroll
        for (int r = 0; r < NN; r++)
            s->A[r][c] = fmaxf(hsum(acc[r]) + bb, 0.f);
    }
    __syncthreads();
    gcn_fused(s, s->A, g_g1w_h, s->Bv, g1b, c);     // A -> Bv
    __syncthreads();
    gcn_fused(s, s->Bv, g_g2w_h, s->A, g2b, c);     // Bv -> A
    __syncthreads();

    // LSTM gates, single pass, fp32 weights: thread c owns cols {c, c+64, c+128, c+192}.
    {
        ull a0[NN] = {}, a1[NN] = {}, a2[NN] = {}, a3[NN] = {};
        #pragma unroll 8
        for (int kq = 0; kq < 16; kq++) {
            ulonglong2 wi0 = ldg4(&g_wih4[(kq * 256 + c) * 4]);
            ulonglong2 wh0 = ldg4(&g_whh4[(kq * 256 + c) * 4]);
            ulonglong2 wi1 = ldg4(&g_wih4[(kq * 256 + 64 + c) * 4]);
            ulonglong2 wh1 = ldg4(&g_whh4[(kq * 256 + 64 + c) * 4]);
            ulonglong2 wi2 = ldg4(&g_wih4[(kq * 256 + 128 + c) * 4]);
            ulonglong2 wh2 = ldg4(&g_whh4[(kq * 256 + 128 + c) * 4]);
            ulonglong2 wi3 = ldg4(&g_wih4[(kq * 256 + 192 + c) * 4]);
            ulonglong2 wh3 = ldg4(&g_whh4[(kq * 256 + 192 + c) * 4]);
            #pragma unroll
            for (int r = 0; r < NN; r++) {
                ulonglong2 aA = lds4(&s->A[r][4 * kq]);
                ulonglong2 aH = lds4(&s->hx[r][4 * kq]);
                ffma2(a0[r], aA.x, wi0.x); ffma2(a0[r], aA.y, wi0.y);
                ffma2(a0[r], aH.x, wh0.x); ffma2(a0[r], aH.y, wh0.y);
                ffma2(a1[r], aA.x, wi1.x); ffma2(a1[r], aA.y, wi1.y);
                ffma2(a1[r], aH.x, wh1.x); ffma2(a1[r], aH.y, wh1.y);
                ffma2(a2[r], aA.x, wi2.x); ffma2(a2[r], aA.y, wi2.y);
                ffma2(a2[r], aH.x, wh2.x); ffma2(a2[r], aH.y, wh2.y);
                ffma2(a3[r], aA.x, wi3.x); ffma2(a3[r], aA.y, wi3.y);
                ffma2(a3[r], aH.x, wh3.x); ffma2(a3[r], aH.y, wh3.y);
            }
        }
        float bI = __ldg(&b_ih[c])       + __ldg(&b_hh[c]);
        float bF = __ldg(&b_ih[64 + c])  + __ldg(&b_hh[64 + c]);
        float bG = __ldg(&b_ih[128 + c]) + __ldg(&b_hh[128 + c]);
        float bO = __ldg(&b_ih[192 + c]) + __ldg(&b_hh[192 + c]);
        __syncthreads();   // all A/hx reads complete before hx overwrite
        #pragma unroll
        for (int r = 0; r < NN; r++) {
            float gi = sigm_f(hsum(a0[r]) + bI);
            float gf = sigm_f(hsum(a1[r]) + bF);
            float gg = tanh_f(hsum(a2[r]) + bG);
            float go = sigm_f(hsum(a3[r]) + bO);
            float cc = gf * s->cx[r][c] + gi * gg;
            s->cx[r][c] = cc;
            s->hx[r][c] = go * tanh_f(cc);
        }
    }
    __syncthreads();
}

__global__ void __launch_bounds__(BT, 8)
stgnn_kernel(const float* __restrict__ xh,    const float* __restrict__ adj,
             const float* __restrict__ enc_b,
             const float* __restrict__ g1b,   const float* __restrict__ g2b,
             const float* __restrict__ b_ih,  const float* __restrict__ b_hh,
             const float* __restrict__ d1b,   const float* __restrict__ d2b,
             float* __restrict__ out) {
    __shared__ Smem sm;
    Smem* s = &sm;
    const int c = threadIdx.x;     // 0..63
    const int b = blockIdx.x;      // batch element

    // ---- normalized adjacency + zero state ----
    if (c < 49) {
        int i = c / 7, j = c - i * 7;
        s->adjn[c] = (i == j) ? 1.0f : __ldg(&adj[b * 49 + c]);
    }
    #pragma unroll
    for (int r = 0; r < NN; r++) { s->hx[r][c] = 0.f; s->cx[r][c] = 0.f; }
    __syncthreads();
    if (c < NN) {
        float sum = 0.f;
        #pragma unroll
        for (int j = 0; j < NN; j++) sum += s->adjn[c * 7 + j];
        s->deg[c] = rsqrtf(fmaxf(sum, 1.0f));
    }
    __syncthreads();
    if (c < 49) {
        int i = c / 7, j = c - i * 7;
        s->adjn[c] *= s->deg[i] * s->deg[j];
    }
    __syncthreads();

    // ---- history scan ----
    #pragma unroll 1
    for (int t = 0; t < T_; t++) {
        for (int idx = c; idx < NN * 12; idx += BT) {
            int r = idx / 12, k = idx - r * 12;
            float v = 0.f;
            if (k < INV) v = __ldg(&xh[((b * T_ + t) * NN + r) * INV + k]);
            s->xt[r][k] = v;
        }
        __syncthreads();
        cell(s, c, enc_b, g1b, g2b, b_ih, b_hh);
    }

    // ---- pred/stat init from last history step ----
    for (int idx = c; idx < NN * INV; idx += BT) {
        int r = idx / INV, k = idx - r * INV;
        float v = __ldg(&xh[((b * T_ + (T_ - 1)) * NN + r) * INV + k]);
        if (k < DYNV) s->pred[r][k] = v;
        else          s->stat[r][k - DYNV] = v;
    }
    __syncthreads();

    // ---- future rollout ----
    #pragma unroll 1
    for (int f = 0; f < FUT; f++) {
        for (int idx = c; idx < NN * 12; idx += BT) {
            int r = idx / 12, k = idx - r * 12;
            float v = 0.f;
            if (k < DYNV)     v = s->pred[r][k];
            else if (k < INV) v = s->stat[r][k - DYNV];
            s->xt[r][k] = v;
        }
        __syncthreads();
        cell(s, c, enc_b, g1b, g2b, b_ih, b_hh);

        // decoder layer 1: Bv[:, :32] = relu(hx @ d1w + d1b); threads 0..31 (fp16 weights)
        if (c < 32) {
            ull acc[NN] = {};
            #pragma unroll
            for (int kq = 0; kq < 16; kq++) {
                ull wx, wy;
                ldgh4(&g_d1w_h[(kq * 32 + c) * 4], wx, wy);
                #pragma unroll
                for (int r = 0; r < NN; r++) {
                    ulonglong2 a = lds4(&s->hx[r][4 * kq]);
                    ffma2(acc[r], a.x, wx);
                    ffma2(acc[r], a.y, wy);
                }
            }
            float bb = __ldg(&d1b[c]);
            #pragma unroll
            for (int r = 0; r < NN; r++)
                s->Bv[r][c] = fmaxf(hsum(acc[r]) + bb, 0.f);
        }
        __syncthreads();

        // decoder layer 2 + residual + clip + output (42 threads)
        if (c < NN * DYNV) {
            int r = c / DYNV, d = c - r * DYNV;
            ull acc = 0;
            float z = 0.f;
            asm("mov.b64 %0, {%1, %1};" : "=l"(acc) : "f"(z));
            #pragma unroll
            for (int kp = 0; kp < 16; kp++)
                ffma2(acc, ldsm2(&s->Bv[r][2 * kp]), ldg2(&g_d2w2[(kp * 6 + d) * 2]));
            float res = tanh_f(hsum(acc) + __ldg(&d2b[d])) * 0.05f;
            float p = fminf(fmaxf(s->pred[r][d] + res, 0.f), 1.f);
            s->pred[r][d] = p;
            out[((b * FUT + f) * NN + r) * DYNV + d] = p;
        }
        __syncthreads();
    }
}

extern "C" void kernel_launch(void* const* d_in, const int* in_sizes, int n_in,
                              void* d_out, int out_size) {
    const float* xh    = (const float*)d_in[0];
    const float* adj   = (const float*)d_in[1];
    const float* enc_w = (const float*)d_in[2];
    const float* enc_b = (const float*)d_in[3];
    const float* g1w   = (const float*)d_in[4];
    const float* g1b   = (const float*)d_in[5];
    const float* g2w   = (const float*)d_in[6];
    const float* g2b   = (const float*)d_in[7];
    const float* w_ih  = (const float*)d_in[8];
    const float* w_hh  = (const float*)d_in[9];
    const float* b_ih  = (const float*)d_in[10];
    const float* b_hh  = (const float*)d_in[11];
    const float* d1w   = (const float*)d_in[12];
    const float* d1b   = (const float*)d_in[13];
    const float* d2w   = (const float*)d_in[14];
    const float* d2b   = (const float*)d_in[15];
    float* out = (float*)d_out;

    pack_weights<<<(23488 + 255) / 256, 256>>>(w_ih, w_hh, g1w, g2w, enc_w, d1w, d2w);
    stgnn_kernel<<<B_, BT>>>(xh, adj, enc_b, g1b, g2b, b_ih, b_hh, d1b, d2b, out);
}

// round 11
// speedup vs baseline: 1.7453x; 1.7453x over previous
#include <cuda_runtime.h>
#include <math.h>

#define B_    4096
#define T_    24
#define NN    7
#define DYNV  6
#define INV   11
#define H     64
#define FUT   48

#define BT    64            // threads per block, one batch element per block
#define HS    68            // padded row stride (floats)

typedef unsigned long long ull;

// Quad-packed fp32 weights: [(kq*C + c)*4 + q] = W[4kq+q][c]
__device__ float g_wih4[16 * 256 * 4];
__device__ float g_whh4[16 * 256 * 4];
__device__ float g_g1w4[16 * 64 * 4];
__device__ float g_g2w4[16 * 64 * 4];
__device__ float g_enc4[3 * 64 * 4];     // k padded 11 -> 12
__device__ float g_d1w4[16 * 32 * 4];
__device__ float g_d2w2[16 * 6 * 2];     // pair-packed (tiny)

__global__ void pack_weights(const float* __restrict__ w_ih, const float* __restrict__ w_hh,
                             const float* __restrict__ g1w,  const float* __restrict__ g2w,
                             const float* __restrict__ enc_w,
                             const float* __restrict__ d1w,  const float* __restrict__ d2w) {
    int i = blockIdx.x * blockDim.x + threadIdx.x;
    if (i < 16384) {
        int q = i & 3, gc = (i >> 2) & 255, kq = i >> 10;
        g_wih4[i] = w_ih[gc * 64 + 4 * kq + q];     // w_ih is [256][64]
        g_whh4[i] = w_hh[gc * 64 + 4 * kq + q];
    } else if (i < 16384 + 4096) {
        int j = i - 16384;
        int q = j & 3, c = (j >> 2) & 63, kq = j >> 8;
        g_g1w4[j] = g1w[(4 * kq + q) * 64 + c];     // g1w is [64][64]
        g_g2w4[j] = g2w[(4 * kq + q) * 64 + c];
    } else if (i < 16384 + 4096 + 768) {
        int j = i - 16384 - 4096;
        int q = j & 3, c = (j >> 2) & 63, kq = j >> 8;
        int k = 4 * kq + q;
        g_enc4[j] = (k < INV) ? enc_w[k * 64 + c] : 0.f;
    } else if (i < 16384 + 4096 + 768 + 2048) {
        int j = i - 16384 - 4096 - 768;
        int q = j & 3, c = (j >> 2) & 31, kq = j >> 7;
        g_d1w4[j] = d1w[(4 * kq + q) * 32 + c];
    } else if (i < 16384 + 4096 + 768 + 2048 + 192) {
        int j = i - (16384 + 4096 + 768 + 2048);
        int kp = j / 12, rr = j - kp * 12, d = rr >> 1, p = rr & 1;
        g_d2w2[j] = d2w[(2 * kp + p) * 6 + d];
    }
}

// ---------- helpers ----------
__device__ __forceinline__ ulonglong2 ldg4(const float* p) {
    return __ldg(reinterpret_cast<const ulonglong2*>(p));
}
__device__ __forceinline__ ulonglong2 lds4(const float* p) {
    return *reinterpret_cast<const ulonglong2*>(p);
}
__device__ __forceinline__ ull ldsm2(const float* p) { return *reinterpret_cast<const ull*>(p); }
__device__ __forceinline__ ull ldg2(const float* p)  { return __ldg(reinterpret_cast<const ull*>(p)); }
__device__ __forceinline__ void ffma2(ull& d, ull a, ull b) {
    asm("fma.rn.f32x2 %0, %1, %2, %3;" : "=l"(d) : "l"(a), "l"(b), "l"(d));
}
__device__ __forceinline__ float hsum(ull v) {
    float2 f = *reinterpret_cast<float2*>(&v);
    return f.x + f.y;
}
__device__ __forceinline__ float sigm_f(float x) { return __fdividef(1.f, 1.f + __expf(-x)); }
__device__ __forceinline__ float tanh_f(float x) {
    float e = __expf(2.f * x);
    return 1.f - __fdividef(2.f, e + 1.f);
}

struct __align__(16) Smem {
    float xt[NN][12];
    float A[NN][HS];
    float Bv[NN][HS];
    float hx[NN][HS];
    float adjn[49];
    float deg[8];
    float pred[NN][DYNV];
    float stat[NN][8];
};

// GCN layer fused: out[i][c] = relu( sum_j adjn[i][j] * (in @ W)[j][c] + bias[c] )
// GEMM intermediate for column c stays in registers of thread c.
__device__ __forceinline__ void gcn_fused(const Smem* s, const float (*in)[HS],
                                          const float* __restrict__ w4,
                                          float (*out)[HS],
                                          const float* __restrict__ bias, int c) {
    ull acc[NN] = {};
    #pragma unroll
    for (int kq = 0; kq < 16; kq++) {
        ulonglong2 w = ldg4(&w4[(kq * 64 + c) * 4]);
        #pragma unroll
        for (int r = 0; r < NN; r++) {
            ulonglong2 a = lds4(&in[r][4 * kq]);
            ffma2(acc[r], a.x, w.x);
            ffma2(acc[r], a.y, w.y);
        }
    }
    float bv[NN];
    #pragma unroll
    for (int r = 0; r < NN; r++) bv[r] = hsum(acc[r]);
    float bb = __ldg(&bias[c]);
    #pragma unroll
    for (int i = 0; i < NN; i++) {
        float a = bb;
        #pragma unroll
        for (int j = 0; j < NN; j++)
            a = fmaf(s->adjn[i * 7 + j], bv[j], a);
        out[i][c] = fmaxf(a, 0.f);
    }
}

// One cell step. xt filled+synced on entry; hx/creg updated+synced on exit.
// creg = this thread's cx[0..6][c] (thread-private state).
__device__ __forceinline__ void cell(Smem* s, int c, float* creg,
        const float* __restrict__ enc_b,
        const float* __restrict__ g1b, const float* __restrict__ g2b,
        const float* __restrict__ b_ih, const float* __restrict__ b_hh) {
    // encoder -> A
    {
        ull acc[NN] = {};
        #pragma unroll
        for (int kq = 0; kq < 3; kq++) {
            ulonglong2 w = ldg4(&g_enc4[(kq * 64 + c) * 4]);
            #pragma unroll
            for (int r = 0; r < NN; r++) {
                ulonglong2 a = lds4(&s->xt[r][4 * kq]);
                ffma2(acc[r], a.x, w.x);
                ffma2(acc[r], a.y, w.y);
            }
        }
        float bb = __ldg(&enc_b[c]);
        #pragma unroll
        for (int r = 0; r < NN; r++)
            s->A[r][c] = fmaxf(hsum(acc[r]) + bb, 0.f);
    }
    __syncthreads();
    gcn_fused(s, s->A, g_g1w4, s->Bv, g1b, c);      // A -> Bv
    __syncthreads();
    gcn_fused(s, s->Bv, g_g2w4, s->A, g2b, c);      // Bv -> A
    __syncthreads();

    // LSTM gates, single pass: thread c owns cols {c, c+64, c+128, c+192}.
    {
        ull a0[NN] = {}, a1[NN] = {}, a2[NN] = {}, a3[NN] = {};
        #pragma unroll 8
        for (int kq = 0; kq < 16; kq++) {
            ulonglong2 wi0 = ldg4(&g_wih4[(kq * 256 + c) * 4]);
            ulonglong2 wh0 = ldg4(&g_whh4[(kq * 256 + c) * 4]);
            ulonglong2 wi1 = ldg4(&g_wih4[(kq * 256 + 64 + c) * 4]);
            ulonglong2 wh1 = ldg4(&g_whh4[(kq * 256 + 64 + c) * 4]);
            ulonglong2 wi2 = ldg4(&g_wih4[(kq * 256 + 128 + c) * 4]);
            ulonglong2 wh2 = ldg4(&g_whh4[(kq * 256 + 128 + c) * 4]);
            ulonglong2 wi3 = ldg4(&g_wih4[(kq * 256 + 192 + c) * 4]);
            ulonglong2 wh3 = ldg4(&g_whh4[(kq * 256 + 192 + c) * 4]);
            #pragma unroll
            for (int r = 0; r < NN; r++) {
                ulonglong2 aA = lds4(&s->A[r][4 * kq]);
                ulonglong2 aH = lds4(&s->hx[r][4 * kq]);
                ffma2(a0[r], aA.x, wi0.x); ffma2(a0[r], aA.y, wi0.y);
                ffma2(a0[r], aH.x, wh0.x); ffma2(a0[r], aH.y, wh0.y);
                ffma2(a1[r], aA.x, wi1.x); ffma2(a1[r], aA.y, wi1.y);
                ffma2(a1[r], aH.x, wh1.x); ffma2(a1[r], aH.y, wh1.y);
                ffma2(a2[r], aA.x, wi2.x); ffma2(a2[r], aA.y, wi2.y);
                ffma2(a2[r], aH.x, wh2.x); ffma2(a2[r], aH.y, wh2.y);
                ffma2(a3[r], aA.x, wi3.x); ffma2(a3[r], aA.y, wi3.y);
                ffma2(a3[r], aH.x, wh3.x); ffma2(a3[r], aH.y, wh3.y);
            }
        }
        float bI = __ldg(&b_ih[c])       + __ldg(&b_hh[c]);
        float bF = __ldg(&b_ih[64 + c])  + __ldg(&b_hh[64 + c]);
        float bG = __ldg(&b_ih[128 + c]) + __ldg(&b_hh[128 + c]);
        float bO = __ldg(&b_ih[192 + c]) + __ldg(&b_hh[192 + c]);
        __syncthreads();   // all A/hx reads complete before hx overwrite
        #pragma unroll
        for (int r = 0; r < NN; r++) {
            float gi = sigm_f(hsum(a0[r]) + bI);
            float gf = sigm_f(hsum(a1[r]) + bF);
            float gg = tanh_f(hsum(a2[r]) + bG);
            float go = sigm_f(hsum(a3[r]) + bO);
            float cc = gf * creg[r] + gi * gg;
            creg[r] = cc;
            s->hx[r][c] = go * tanh_f(cc);
        }
    }
    __syncthreads();
}

__global__ void __launch_bounds__(BT, 8)
stgnn_kernel(const float* __restrict__ xh,    const float* __restrict__ adj,
             const float* __restrict__ enc_b,
             const float* __restrict__ g1b,   const float* __restrict__ g2b,
             const float* __restrict__ b_ih,  const float* __restrict__ b_hh,
             const float* __restrict__ d1b,   const float* __restrict__ d2b,
             float* __restrict__ out) {
    __shared__ Smem sm;
    Smem* s = &sm;
    const int c = threadIdx.x;     // 0..63
    const int b = blockIdx.x;      // batch element

    // ---- normalized adjacency + zero state ----
    if (c < 49) {
        int i = c / 7, j = c - i * 7;
        s->adjn[c] = (i == j) ? 1.0f : __ldg(&adj[b * 49 + c]);
    }
    float creg[NN];                // cx[0..6][c] in registers (thread-private)
    #pragma unroll
    for (int r = 0; r < NN; r++) { s->hx[r][c] = 0.f; creg[r] = 0.f; }
    __syncthreads();
    if (c < NN) {
        float sum = 0.f;
        #pragma unroll
        for (int j = 0; j < NN; j++) sum += s->adjn[c * 7 + j];
        s->deg[c] = rsqrtf(fmaxf(sum, 1.0f));
    }
    __syncthreads();
    if (c < 49) {
        int i = c / 7, j = c - i * 7;
        s->adjn[c] *= s->deg[i] * s->deg[j];
    }
    __syncthreads();

    // ---- history scan ----
    #pragma unroll 1
    for (int t = 0; t < T_; t++) {
        for (int idx = c; idx < NN * 12; idx += BT) {
            int r = idx / 12, k = idx - r * 12;
            float v = 0.f;
            if (k < INV) v = __ldg(&xh[((b * T_ + t) * NN + r) * INV + k]);
            s->xt[r][k] = v;
        }
        __syncthreads();
        cell(s, c, creg, enc_b, g1b, g2b, b_ih, b_hh);
    }

    // ---- pred/stat init from last history step ----
    for (int idx = c; idx < NN * INV; idx += BT) {
        int r = idx / INV, k = idx - r * INV;
        float v = __ldg(&xh[((b * T_ + (T_ - 1)) * NN + r) * INV + k]);
        if (k < DYNV) s->pred[r][k] = v;
        else          s->stat[r][k - DYNV] = v;
    }
    __syncthreads();

    // ---- future rollout ----
    #pragma unroll 1
    for (int f = 0; f < FUT; f++) {
        for (int idx = c; idx < NN * 12; idx += BT) {
            int r = idx / 12, k = idx - r * 12;
            float v = 0.f;
            if (k < DYNV)     v = s->pred[r][k];
            else if (k < INV) v = s->stat[r][k - DYNV];
            s->xt[r][k] = v;
        }
        __syncthreads();
        cell(s, c, creg, enc_b, g1b, g2b, b_ih, b_hh);

        // decoder layer 1: Bv[:, :32] = relu(hx @ d1w + d1b); ALL 64 threads.
        // thread c: col = c&31, rows {0..3} if c<32 else {4..6}.
        {
            int col = c & 31;
            int r0 = (c < 32) ? 0 : 4;
            int nr = (c < 32) ? 4 : 3;
            ull acc[4] = {};
            #pragma unroll
            for (int kq = 0; kq < 16; kq++) {
                ulonglong2 w = ldg4(&g_d1w4[(kq * 32 + col) * 4]);
                #pragma unroll
                for (int i = 0; i < 4; i++) {
                    if (i < nr) {
                        ulonglong2 a = lds4(&s->hx[r0 + i][4 * kq]);
                        ffma2(acc[i], a.x, w.x);
                        ffma2(acc[i], a.y, w.y);
                    }
                }
            }
            float bb = __ldg(&d1b[col]);
            #pragma unroll
            for (int i = 0; i < 4; i++)
                if (i < nr)
                    s->Bv[r0 + i][col] = fmaxf(hsum(acc[i]) + bb, 0.f);
        }
        __syncthreads();

        // decoder layer 2 + residual + clip + output (42 threads)
        if (c < NN * DYNV) {
            int r = c / DYNV, d = c - r * DYNV;
            ull acc = 0;
            float z = 0.f;
            asm("mov.b64 %0, {%1, %1};" : "=l"(acc) : "f"(z));
            #pragma unroll
            for (int kp = 0; kp < 16; kp++)
                ffma2(acc, ldsm2(&s->Bv[r][2 * kp]), ldg2(&g_d2w2[(kp * 6 + d) * 2]));
            float res = tanh_f(hsum(acc) + __ldg(&d2b[d])) * 0.05f;
            float p = fminf(fmaxf(s->pred[r][d] + res, 0.f), 1.f);
            s->pred[r][d] = p;
            out[((b * FUT + f) * NN + r) * DYNV + d] = p;
        }
        __syncthreads();
    }
}

extern "C" void kernel_launch(void* const* d_in, const int* in_sizes, int n_in,
                              void* d_out, int out_size) {
    const float* xh    = (const float*)d_in[0];
    const float* adj   = (const float*)d_in[1];
    const float* enc_w = (const float*)d_in[2];
    const float* enc_b = (const float*)d_in[3];
    const float* g1w   = (const float*)d_in[4];
    const float* g1b   = (const float*)d_in[5];
    const float* g2w   = (const float*)d_in[6];
    const float* g2b   = (const float*)d_in[7];
    const float* w_ih  = (const float*)d_in[8];
    const float* w_hh  = (const float*)d_in[9];
    const float* b_ih  = (const float*)d_in[10];
    const float* b_hh  = (const float*)d_in[11];
    const float* d1w   = (const float*)d_in[12];
    const float* d1b   = (const float*)d_in[13];
    const float* d2w   = (const float*)d_in[14];
    const float* d2b   = (const float*)d_in[15];
    float* out = (float*)d_out;

    pack_weights<<<(23488 + 255) / 256, 256>>>(w_ih, w_hh, g1w, g2w, enc_w, d1w, d2w);
    stgnn_kernel<<<B_, BT>>>(xh, adj, enc_b, g1b, g2b, b_ih, b_hh, d1b, d2b, out);
}